// round 6
// baseline (speedup 1.0000x reference)
#include <cuda_runtime.h>
#include <cuda_bf16.h>

#define KK 7
#define C1 21
#define NBINS 49            // KK*KK
#define HF 128
#define WF 128
#define PLANE (HF*WF)       // 16384
#define FEAT_STRIDE 30
#define MAX_YSTEP 9         // rois: (ymax-ymin) <= 63 -> ystep <= 9

// P layout: [g][y][slot][cc] with slot = x+1 (slot 0 is an all-zero column so
// the left-corner read at xs=0 needs no predication).
#define ROWP 2712           // 129*21 = 2709 padded to float4 multiple
#define PLANEP (HF*ROWP)    // 347136 floats per bin-group

// +64 pad: K2 lets lanes 21..31 issue (unused) loads up to +31 past the end.
// Static __device__ storage is zero-initialized, so pad/tail words are 0.
__device__ float g_prefix[NBINS * PLANEP + 64];

// smem row stride for K1 [cc][x] tile: 132 words (528B = 33*16, float4-aligned)
#define SROW 132

// ---------------------------------------------------------------------------
// K1: NCHW -> [g][y][x+1][cc] transpose fused with inclusive x-prefix-sum.
// One block per (g, y), 224 threads = 7 warps; warp w scans class rows
// 3w..3w+2 (uniform load). Scan in registers, one contiguous STS.128 per
// lane per row (conflict-free), then copy-out with arithmetic zero-column.
// ---------------------------------------------------------------------------
__global__ __launch_bounds__(224)
void psroi_transpose_scan_kernel(const float* __restrict__ fmap,
                                 float* __restrict__ P)
{
    const int g = blockIdx.x >> 7;        // 0..48
    const int y = blockIdx.x & 127;       // 0..127
    const int t = threadIdx.x;
    const int warp = t >> 5;
    const int lane = t & 31;

    __shared__ __align__(16) float tile[C1 * SROW];   // [cc][x], x=0..127

    #pragma unroll
    for (int r = 0; r < 3; ++r) {
        const int cc = warp * 3 + r;      // 0..20, exactly covered
        const float4* src = (const float4*)(fmap + (size_t)(g * C1 + cc) * PLANE + y * WF);
        float4 v = __ldg(src + lane);
        float a0 = v.x;
        float a1 = a0 + v.y;
        float a2 = a1 + v.z;
        float a3 = a2 + v.w;
        float s = a3;
        #pragma unroll
        for (int d = 1; d < 32; d <<= 1) {
            float u = __shfl_up_sync(0xffffffff, s, d);
            if (lane >= d) s += u;
        }
        float excl = __shfl_up_sync(0xffffffff, s, 1);
        if (lane == 0) excl = 0.0f;

        // contiguous 512B per warp: conflict-free STS.128
        *(float4*)&tile[cc * SROW + 4 * lane] =
            make_float4(excl + a0, excl + a1, excl + a2, excl + a3);
    }
    __syncthreads();

    // copy-out: 2709 words [slot*21+cc], slot=0 column emitted as 0.0f
    float* dst = P + (unsigned)g * PLANEP + (unsigned)y * ROWP;
    for (unsigned o = t; o < 129u * C1; o += 224) {
        const unsigned slot = o / C1;
        const unsigned cc   = o - slot * C1;
        dst[o] = slot ? tile[cc * SROW + slot - 1] : 0.0f;
    }
}

// ---------------------------------------------------------------------------
// K2: one WARP per ROI. Lane = class (lanes 21..31 compute garbage that is
// masked out). Walks 49 bins with strength-reduced offsets; dy unrolled 9x
// predicated (18 loads in flight per bin). Accumulates the class-mean
// numerator in registers; softmax via shuffles. No smem, no barriers.
// ---------------------------------------------------------------------------
__global__ __launch_bounds__(64)
void psroi_pool_kernel(const float* __restrict__ P,
                       const int* __restrict__ rois,
                       float* __restrict__ out,
                       int n_rois)
{
    const int roi = blockIdx.x * 2 + (threadIdx.x >> 5);
    if (roi >= n_rois) return;
    const int lane = threadIdx.x & 31;

    const int4 rr = __ldg(((const int4*)rois) + roi);
    const unsigned ymin = (unsigned)rr.x / FEAT_STRIDE;
    const unsigned xmin = (unsigned)rr.y / FEAT_STRIDE;
    const unsigned ymax = (unsigned)rr.z / FEAT_STRIDE;
    const unsigned xmax = (unsigned)rr.w / FEAT_STRIDE;
    const int ystep = (int)((ymax - ymin) / KK);
    const int xstep = (int)((xmax - xmin) / KK);
    const bool has_area = (ystep > 0) && (xstep > 0);

    float v0 = 0.0f, v1 = 0.0f;
    if (has_area) {
        const unsigned dl = (unsigned)xstep * C1;
        // g=0 right corner: slot = xmin + xstep
        unsigned offR = ymin * ROWP + (xmin + (unsigned)xstep) * C1 + lane;
        const unsigned jfix = (unsigned)ystep * ROWP - 7u * dl;

        #pragma unroll 1
        for (int j = 0; j < KK; ++j) {
            #pragma unroll
            for (int l = 0; l < KK; ++l) {
                const unsigned offL = offR - dl;
                #pragma unroll
                for (int dy = 0; dy < MAX_YSTEP; ++dy) {
                    if (dy < ystep) {
                        float d = __ldg(P + offR + dy * ROWP)
                                - __ldg(P + offL + dy * ROWP);
                        if (dy & 1) v1 += d; else v0 += d;
                    }
                }
                offR += PLANEP + dl;      // g+1, xe += xstep
            }
            offR += jfix;                 // ys += ystep, reset xe
        }
    }

    const float inv_area = has_area ? (1.0f / (float)(ystep * xstep)) : 0.0f;
    float v = (lane < C1) ? (v0 + v1) * inv_area * (1.0f / (float)NBINS) : -1e30f;

    // softmax over 21 classes within the warp
    float mx = v;
    #pragma unroll
    for (int o = 16; o; o >>= 1)
        mx = fmaxf(mx, __shfl_xor_sync(0xffffffff, mx, o));
    float e = (lane < C1) ? __expf(v - mx) : 0.0f;
    float sm = e;
    #pragma unroll
    for (int o = 16; o; o >>= 1)
        sm += __shfl_xor_sync(0xffffffff, sm, o);
    if (lane < C1)
        out[roi * C1 + lane] = e / sm;
}

extern "C" void kernel_launch(void* const* d_in, const int* in_sizes, int n_in,
                              void* d_out, int out_size)
{
    const float* fmap = (const float*)d_in[0];   // (1, 1029, 128, 128) fp32
    const int*   rois = (const int*)d_in[1];     // (N, 4) int32
    float* out = (float*)d_out;                  // (N, 21) fp32
    const int n_rois = in_sizes[1] / 4;

    float* P;
    cudaGetSymbolAddress((void**)&P, g_prefix);

    psroi_transpose_scan_kernel<<<NBINS * HF, 224>>>(fmap, P);
    psroi_pool_kernel<<<(n_rois + 1) / 2, 64>>>(P, rois, out, n_rois);
}

// round 7
// speedup vs baseline: 1.9199x; 1.9199x over previous
#include <cuda_runtime.h>
#include <cuda_bf16.h>

#define KK 7
#define C1 21
#define NBINS 49            // KK*KK
#define NCH 1029            // NBINS*C1
#define HF 128
#define WF 128
#define PLANE (HF*WF)       // 16384
#define FEAT_STRIDE 30
#define MAX_YSTEP 9         // rois: ystep <= 9 by construction

// P layout: [g][y][slot][cc] with slot = x+1 (slot 0 is an all-zero column so
// the left-corner read at xs=0 needs no predication).
#define ROWP 2712           // 129*21 = 2709 padded to float4 multiple
#define PLANEP (HF*ROWP)    // 347136 floats per bin-group

// ~68 MB scratch
__device__ float g_prefix[NBINS * PLANEP];

// ---------------------------------------------------------------------------
// K1: NCHW -> [g][y][x+1][cc] transpose fused with inclusive x-prefix-sum.
// One block per (g, y), 256 threads (8 warps). Register-resident warp scan,
// transpose via smem, contiguous float4 stream out.
// fmap is read ONCE per replay -> __ldcs (evict-first) so the 64MB stream
// does not evict P from L2 before K2 reads it.
// ---------------------------------------------------------------------------
__global__ __launch_bounds__(256)
void psroi_transpose_scan_kernel(const float* __restrict__ fmap,
                                 float* __restrict__ P)
{
    const int g = blockIdx.x >> 7;        // 0..48
    const int y = blockIdx.x & 127;       // 0..127
    const int t = threadIdx.x;
    const int warp = t >> 5;
    const int lane = t & 31;

    __shared__ float tile2[ROWP];         // [(x+1)*21 + cc]

    if (t < C1) tile2[t] = 0.0f;                               // zero column
    if (t >= 32 && t < 35) tile2[ROWP - 3 + (t - 32)] = 0.0f;  // tail pad

    for (int cc = warp; cc < C1; cc += 8) {
        const float4* src = (const float4*)(fmap + (size_t)(g * C1 + cc) * PLANE + y * WF);
        float4 v = __ldcs(src + lane);    // evict-first: single-use stream
        float a0 = v.x;
        float a1 = a0 + v.y;
        float a2 = a1 + v.z;
        float a3 = a2 + v.w;
        float s = a3;
        #pragma unroll
        for (int d = 1; d < 32; d <<= 1) {
            float u = __shfl_up_sync(0xffffffff, s, d);
            if (lane >= d) s += u;
        }
        float excl = __shfl_up_sync(0xffffffff, s, 1);
        if (lane == 0) excl = 0.0f;

        const int slot = 4 * lane + 1;    // x+1
        tile2[(slot + 0) * C1 + cc] = excl + a0;
        tile2[(slot + 1) * C1 + cc] = excl + a1;
        tile2[(slot + 2) * C1 + cc] = excl + a2;
        tile2[(slot + 3) * C1 + cc] = excl + a3;
    }
    __syncthreads();

    float4* dst4 = (float4*)(P + (size_t)g * PLANEP + y * ROWP);
    const float4* s4 = (const float4*)tile2;
    #pragma unroll
    for (int i = t; i < ROWP / 4; i += 256)
        dst4[i] = s4[i];
}

// ---------------------------------------------------------------------------
// K2: pooling + mean + softmax. One block per ROI, 1024 threads.
// Thread = flat channel c = g*21+cc. 32-bit indexing; dy loop unrolled with
// predication. ystep is uniform across the block, so branch (no divergence)
// into a 4-deep or 9-deep unrolled body to halve predicated LDG slots for
// small ROIs.
// ---------------------------------------------------------------------------
__global__ __launch_bounds__(1024)
void psroi_pool_kernel(const float* __restrict__ P,
                       const int* __restrict__ rois,
                       float* __restrict__ out)
{
    const int n = blockIdx.x;
    const int t = threadIdx.x;

    __shared__ float pool[NCH];

    const int4 rr = __ldg(((const int4*)rois) + n);
    const unsigned ymin = (unsigned)rr.x / FEAT_STRIDE;
    const unsigned xmin = (unsigned)rr.y / FEAT_STRIDE;
    const unsigned ymax = (unsigned)rr.z / FEAT_STRIDE;
    const unsigned xmax = (unsigned)rr.w / FEAT_STRIDE;
    const int ystep = (int)((ymax - ymin) / KK);
    const int xstep = (int)((xmax - xmin) / KK);
    const bool has_area = (ystep > 0) && (xstep > 0);
    const float inv_area = has_area ? (1.0f / (float)(ystep * xstep)) : 0.0f;

    for (unsigned c = t; c < NCH; c += 1024) {
        const unsigned g  = c / C1;
        const unsigned cc = c - g * C1;
        const unsigned j  = g / KK;
        const unsigned l  = g - j * KK;
        const unsigned ys = ymin + j * ystep;
        const unsigned xs = xmin + l * xstep;
        const unsigned xe = xs + xstep;    // right corner slot index

        float acc = 0.0f;
        if (has_area) {
            const unsigned offR = g * PLANEP + ys * ROWP + xe * C1 + cc;
            const unsigned offL = offR - (unsigned)(xstep * C1);  // left slot = xs
            if (ystep <= 4) {
                #pragma unroll
                for (int dy = 0; dy < 4; ++dy)
                    if (dy < ystep)
                        acc += __ldg(P + offR + dy * ROWP) - __ldg(P + offL + dy * ROWP);
            } else {
                #pragma unroll
                for (int dy = 0; dy < MAX_YSTEP; ++dy)
                    if (dy < ystep)
                        acc += __ldg(P + offR + dy * ROWP) - __ldg(P + offL + dy * ROWP);
            }
            acc *= inv_area;
        }
        pool[c] = acc;
    }
    __syncthreads();

    // Per-class mean over 49 bins + softmax over 21 classes (warp 0 only)
    if (t < 32) {
        float v = -1e30f;
        if (t < C1) {
            float s = 0.0f;
            #pragma unroll
            for (int g = 0; g < NBINS; ++g)
                s += pool[g * C1 + t];
            v = s * (1.0f / (float)NBINS);
        }
        float mx = v;
        #pragma unroll
        for (int o = 16; o; o >>= 1)
            mx = fmaxf(mx, __shfl_xor_sync(0xffffffff, mx, o));
        float e = (t < C1) ? __expf(v - mx) : 0.0f;
        float sm = e;
        #pragma unroll
        for (int o = 16; o; o >>= 1)
            sm += __shfl_xor_sync(0xffffffff, sm, o);
        if (t < C1)
            out[n * C1 + t] = e / sm;
    }
}

extern "C" void kernel_launch(void* const* d_in, const int* in_sizes, int n_in,
                              void* d_out, int out_size)
{
    const float* fmap = (const float*)d_in[0];   // (1, 1029, 128, 128) fp32
    const int*   rois = (const int*)d_in[1];     // (N, 4) int32
    float* out = (float*)d_out;                  // (N, 21) fp32
    const int n_rois = in_sizes[1] / 4;

    float* P;
    cudaGetSymbolAddress((void**)&P, g_prefix);

    psroi_transpose_scan_kernel<<<NBINS * HF, 256>>>(fmap, P);
    psroi_pool_kernel<<<n_rois, 1024>>>(P, rois, out);
}

// round 8
// speedup vs baseline: 2.1942x; 1.1429x over previous
#include <cuda_runtime.h>
#include <cuda_bf16.h>

#define KK 7
#define C1 21
#define C1S 22              // padded class stride (even -> float2-aligned)
#define NBINS 49            // KK*KK
#define HF 128
#define WF 128
#define PLANE (HF*WF)       // 16384
#define FEAT_STRIDE 30
#define MAX_YSTEP 9         // rois: ystep <= 9 by construction

// P layout: [g][y][slot][ccp] with slot = x+1 (slot 0 all-zero so xs=0 left
// corner needs no predication), ccp = 0..21 (21 = pad, always 0).
#define ROWP (129*C1S)      // 2838
#define PLANEP (HF*ROWP)    // 363264 floats per bin-group

// ~71.2 MB scratch (zero-initialized static storage)
__device__ float g_prefix[NBINS * PLANEP];

// K1 smem tile: [cc][x], row stride 132 words (16B-aligned, conflict-free STS.128)
#define SROW 132

// ---------------------------------------------------------------------------
// K1: NCHW -> [g][y][x+1][ccp] transpose + inclusive x-prefix-sum.
// Block per (g, y), 224 threads = 7 warps x 3 class rows (exact).
// Scan in registers (fmap via __ldcs: single-use stream, keep P in L2),
// conflict-free STS.128 into [cc][x] tile, transposed scalar copy-out.
// ---------------------------------------------------------------------------
__global__ __launch_bounds__(224)
void psroi_transpose_scan_kernel(const float* __restrict__ fmap,
                                 float* __restrict__ P)
{
    const int g = blockIdx.x >> 7;        // 0..48
    const int y = blockIdx.x & 127;       // 0..127
    const int t = threadIdx.x;
    const int warp = t >> 5;
    const int lane = t & 31;

    __shared__ __align__(16) float tile[C1 * SROW];   // inclusive prefix, [cc][x]

    #pragma unroll
    for (int r = 0; r < 3; ++r) {
        const int cc = warp * 3 + r;      // 0..20 exact
        const float4* src = (const float4*)(fmap + (size_t)(g * C1 + cc) * PLANE + y * WF);
        float4 v = __ldcs(src + lane);
        float a0 = v.x;
        float a1 = a0 + v.y;
        float a2 = a1 + v.z;
        float a3 = a2 + v.w;
        float s = a3;
        #pragma unroll
        for (int d = 1; d < 32; d <<= 1) {
            float u = __shfl_up_sync(0xffffffff, s, d);
            if (lane >= d) s += u;
        }
        float excl = __shfl_up_sync(0xffffffff, s, 1);
        if (lane == 0) excl = 0.0f;

        *(float4*)&tile[cc * SROW + 4 * lane] =
            make_float4(excl + a0, excl + a1, excl + a2, excl + a3);
    }
    __syncthreads();

    // copy-out: 2838 words [slot*22 + ccp]; slot0 column and ccp=21 pad are 0
    float* dst = P + (unsigned)g * PLANEP + (unsigned)y * ROWP;
    for (unsigned o = t; o < (unsigned)ROWP; o += 224) {
        const unsigned slot = o / C1S;
        const unsigned cc   = o - slot * C1S;
        float v = 0.0f;
        if (slot != 0u && cc < C1)
            v = tile[cc * SROW + slot - 1];
        dst[o] = v;
    }
}

// ---------------------------------------------------------------------------
// K2: pooling + mean + softmax. Block per ROI, 576 threads.
// Threads 0..48 precompute per-bin right-corner base offsets into smem.
// Threads 0..538: (g, class-pair q) -> two float2 corner loads per dy
// (predicated unroll, ystep uniform branch). Warp 0 does mean + softmax.
// ---------------------------------------------------------------------------
__global__ __launch_bounds__(576)
void psroi_pool_kernel(const float* __restrict__ P,
                       const int* __restrict__ rois,
                       float* __restrict__ out)
{
    const int n = blockIdx.x;
    const int t = threadIdx.x;

    __shared__ unsigned binoff[NBINS];
    __shared__ __align__(8) float pool[NBINS * C1S];

    const int4 rr = __ldg(((const int4*)rois) + n);
    const unsigned ymin = (unsigned)rr.x / FEAT_STRIDE;
    const unsigned xmin = (unsigned)rr.y / FEAT_STRIDE;
    const unsigned ymax = (unsigned)rr.z / FEAT_STRIDE;
    const unsigned xmax = (unsigned)rr.w / FEAT_STRIDE;
    const int ystep = (int)((ymax - ymin) / KK);
    const int xstep = (int)((xmax - xmin) / KK);
    const bool has_area = (ystep > 0) && (xstep > 0);
    const float inv_area = has_area ? (1.0f / (float)(ystep * xstep)) : 0.0f;

    if (t < NBINS) {
        const unsigned j = (unsigned)t / KK;
        const unsigned l = (unsigned)t - j * KK;
        const unsigned ys = ymin + j * (unsigned)ystep;
        const unsigned xe = xmin + (l + 1u) * (unsigned)xstep;   // right slot
        binoff[t] = (unsigned)t * PLANEP + ys * ROWP + xe * C1S;
    }
    __syncthreads();

    if (t < NBINS * 11) {
        const unsigned g = (unsigned)t / 11u;
        const unsigned q = (unsigned)t - g * 11u;
        const unsigned co = 2u * q;                 // class pair base
        float ax = 0.0f, ay = 0.0f;
        if (has_area) {
            const unsigned dlw  = (unsigned)xstep * C1S;
            const unsigned offR = binoff[g] + co;
            const unsigned offL = offR - dlw;       // left slot (slot0 = zeros)
            if (ystep <= 4) {
                #pragma unroll
                for (int dy = 0; dy < 4; ++dy)
                    if (dy < ystep) {
                        float2 r = __ldg((const float2*)(P + offR + dy * ROWP));
                        float2 lf = __ldg((const float2*)(P + offL + dy * ROWP));
                        ax += r.x - lf.x;
                        ay += r.y - lf.y;
                    }
            } else {
                #pragma unroll
                for (int dy = 0; dy < MAX_YSTEP; ++dy)
                    if (dy < ystep) {
                        float2 r = __ldg((const float2*)(P + offR + dy * ROWP));
                        float2 lf = __ldg((const float2*)(P + offL + dy * ROWP));
                        ax += r.x - lf.x;
                        ay += r.y - lf.y;
                    }
            }
        }
        *(float2*)&pool[g * C1S + co] = make_float2(ax * inv_area, ay * inv_area);
    }
    __syncthreads();

    // Per-class mean over 49 bins + softmax over 21 classes (warp 0 only)
    if (t < 32) {
        float v = -1e30f;
        if (t < C1) {
            float s = 0.0f;
            #pragma unroll
            for (int g = 0; g < NBINS; ++g)
                s += pool[g * C1S + t];
            v = s * (1.0f / (float)NBINS);
        }
        float mx = v;
        #pragma unroll
        for (int o = 16; o; o >>= 1)
            mx = fmaxf(mx, __shfl_xor_sync(0xffffffff, mx, o));
        float e = (t < C1) ? __expf(v - mx) : 0.0f;
        float sm = e;
        #pragma unroll
        for (int o = 16; o; o >>= 1)
            sm += __shfl_xor_sync(0xffffffff, sm, o);
        if (t < C1)
            out[n * C1 + t] = e / sm;
    }
}

extern "C" void kernel_launch(void* const* d_in, const int* in_sizes, int n_in,
                              void* d_out, int out_size)
{
    const float* fmap = (const float*)d_in[0];   // (1, 1029, 128, 128) fp32
    const int*   rois = (const int*)d_in[1];     // (N, 4) int32
    float* out = (float*)d_out;                  // (N, 21) fp32
    const int n_rois = in_sizes[1] / 4;

    float* P;
    cudaGetSymbolAddress((void**)&P, g_prefix);

    psroi_transpose_scan_kernel<<<NBINS * HF, 224>>>(fmap, P);
    psroi_pool_kernel<<<n_rois, 576>>>(P, rois, out);
}